// round 1
// baseline (speedup 1.0000x reference)
#include <cuda_runtime.h>
#include <math.h>

#define B_  4
#define H_  16
#define LQ_ 512
#define LK_ 2048
#define DM_ 1024
#define DH_ 64

// Scratch (device globals; no runtime allocation allowed)
__device__ float g_q [(size_t)B_*H_*LQ_*DH_];   //  8 MB  [B,H,LQ,64]
__device__ float g_k [(size_t)B_*H_*LK_*DH_];   // 32 MB  [B,H,LK,64]
__device__ float g_v [(size_t)B_*H_*LK_*DH_];   // 32 MB  [B,H,LK,64]
__device__ float g_ao[(size_t)B_*LQ_*H_*DH_];   //  8 MB  [B,LQ,H*64]
__device__ float g_y [(size_t)B_*LQ_*DM_];      //  8 MB  pre-LN

// ---------------------------------------------------------------------------
// Tiled fp32 GEMM: out = X[rows,1024] @ W[1024,1024] + bias (+resid)
// Tile 64x64, BK=16, 16x16 threads, 4x4 micro-tile.
// outMode: 0 -> g_q head layout, 1 -> g_k, 2 -> g_v (head layout, per-batch L)
//          3 -> g_y plain [rows,1024] (X is taken from g_ao, resid added)
// ---------------------------------------------------------------------------
__global__ void gemm64(const float* __restrict__ X,
                       const float* __restrict__ W,
                       const float* __restrict__ bias,
                       const float* __restrict__ resid,
                       int rows, int L, int outMode)
{
    __shared__ __align__(16) float As[16][64];
    __shared__ __align__(16) float Bs[16][64];

    const float* Xp = (outMode == 3) ? (const float*)g_ao : X;

    const int row0 = blockIdx.y * 64;
    const int col0 = blockIdx.x * 64;
    const int tx = threadIdx.x, ty = threadIdx.y;
    const int tid = ty * 16 + tx;

    float acc[4][4] = {};

    for (int k0 = 0; k0 < DM_; k0 += 16) {
        #pragma unroll
        for (int s = 0; s < 4; s++) {
            int idx = tid + s * 256;
            int m  = idx >> 4, kk  = idx & 15;
            As[kk][m] = Xp[(size_t)(row0 + m) * DM_ + k0 + kk];
            int kk2 = idx >> 6, n = idx & 63;
            Bs[kk2][n] = W[(size_t)(k0 + kk2) * DM_ + col0 + n];
        }
        __syncthreads();

        #pragma unroll
        for (int kk = 0; kk < 16; kk++) {
            float4 a = *(const float4*)&As[kk][ty * 4];
            float4 b = *(const float4*)&Bs[kk][tx * 4];
            acc[0][0] += a.x * b.x; acc[0][1] += a.x * b.y; acc[0][2] += a.x * b.z; acc[0][3] += a.x * b.w;
            acc[1][0] += a.y * b.x; acc[1][1] += a.y * b.y; acc[1][2] += a.y * b.z; acc[1][3] += a.y * b.w;
            acc[2][0] += a.z * b.x; acc[2][1] += a.z * b.y; acc[2][2] += a.z * b.z; acc[2][3] += a.z * b.w;
            acc[3][0] += a.w * b.x; acc[3][1] += a.w * b.y; acc[3][2] += a.w * b.z; acc[3][3] += a.w * b.w;
        }
        __syncthreads();
    }

    float* outHead = (outMode == 0) ? g_q : (outMode == 1) ? g_k : g_v;

    #pragma unroll
    for (int i = 0; i < 4; i++) {
        int row = row0 + ty * 4 + i;
        #pragma unroll
        for (int j = 0; j < 4; j++) {
            int n = col0 + tx * 4 + j;
            float val = acc[i][j] + bias[n];
            if (outMode == 3) {
                val += resid[(size_t)row * DM_ + n];
                g_y[(size_t)row * DM_ + n] = val;
            } else {
                int b = row / L, l = row % L;
                int h = n >> 6, d = n & 63;
                outHead[(((size_t)(b * H_ + h) * L) + l) * DH_ + d] = val;
            }
        }
    }
}

// ---------------------------------------------------------------------------
// Attention: one block per (q, h, b). 256 threads.
// scores in smem, block softmax, 4-way split AV accumulation.
// ---------------------------------------------------------------------------
__global__ void attn_kernel(const int* __restrict__ mask)
{
    const int qi = blockIdx.x, h = blockIdx.y, b = blockIdx.z;
    const int tid = threadIdx.x;

    __shared__ float sc[LK_];
    __shared__ __align__(16) float qv[DH_];
    __shared__ float red[256];

    const float* qrow = g_q + (((size_t)(b * H_ + h) * LQ_) + qi) * DH_;
    if (tid < DH_) qv[tid] = qrow[tid];
    __syncthreads();

    const float* kb = g_k + (size_t)(b * H_ + h) * LK_ * DH_;
    float lmax = -1e30f;
    for (int j = tid; j < LK_; j += 256) {
        const float* kr = kb + (size_t)j * DH_;
        float dot = 0.f;
        #pragma unroll
        for (int d = 0; d < DH_; d += 4) {
            float4 kvv = *(const float4*)(kr + d);
            dot += qv[d] * kvv.x + qv[d + 1] * kvv.y + qv[d + 2] * kvv.z + qv[d + 3] * kvv.w;
        }
        float s = (mask[b * LK_ + j] == 0) ? -1e30f : dot * 0.125f;
        sc[j] = s;
        lmax = fmaxf(lmax, s);
    }

    red[tid] = lmax; __syncthreads();
    #pragma unroll
    for (int s = 128; s > 0; s >>= 1) {
        if (tid < s) red[tid] = fmaxf(red[tid], red[tid + s]);
        __syncthreads();
    }
    float mx = red[0];
    __syncthreads();

    float lsum = 0.f;
    for (int j = tid; j < LK_; j += 256) {
        float e = __expf(sc[j] - mx);
        sc[j] = e;
        lsum += e;
    }
    red[tid] = lsum; __syncthreads();
    #pragma unroll
    for (int s = 128; s > 0; s >>= 1) {
        if (tid < s) red[tid] += red[tid + s];
        __syncthreads();
    }
    float inv = 1.0f / red[0];
    __syncthreads();

    const float* vb = g_v + (size_t)(b * H_ + h) * LK_ * DH_;
    int g = tid >> 6, d = tid & 63;
    float acc = 0.f;
    for (int j = g; j < LK_; j += 4)
        acc += sc[j] * vb[(size_t)j * DH_ + d];

    red[tid] = acc; __syncthreads();
    if (tid < DH_) {
        float o = (red[tid] + red[64 + tid] + red[128 + tid] + red[192 + tid]) * inv;
        g_ao[(((size_t)b * LQ_ + qi) * H_ + h) * DH_ + tid] = o;
    }
}

// ---------------------------------------------------------------------------
// LayerNorm per row of g_y, write final output
// ---------------------------------------------------------------------------
__global__ void layernorm_kernel(const float* __restrict__ gamma,
                                 const float* __restrict__ beta,
                                 float* __restrict__ out)
{
    const int row = blockIdx.x;
    const int tid = threadIdx.x;
    __shared__ float red[256];

    const float* yr = g_y + (size_t)row * DM_;
    float4 xv = *(const float4*)(yr + tid * 4);

    float s = xv.x + xv.y + xv.z + xv.w;
    red[tid] = s; __syncthreads();
    #pragma unroll
    for (int st = 128; st > 0; st >>= 1) {
        if (tid < st) red[tid] += red[tid + st];
        __syncthreads();
    }
    float mean = red[0] * (1.0f / DM_);
    __syncthreads();

    float dx = xv.x - mean, dy = xv.y - mean, dz = xv.z - mean, dw = xv.w - mean;
    float sq = dx * dx + dy * dy + dz * dz + dw * dw;
    red[tid] = sq; __syncthreads();
    #pragma unroll
    for (int st = 128; st > 0; st >>= 1) {
        if (tid < st) red[tid] += red[tid + st];
        __syncthreads();
    }
    float rstd = rsqrtf(red[0] * (1.0f / DM_) + 1e-5f);

    int n = tid * 4;
    float4 ov;
    ov.x = dx * rstd * gamma[n]     + beta[n];
    ov.y = dy * rstd * gamma[n + 1] + beta[n + 1];
    ov.z = dz * rstd * gamma[n + 2] + beta[n + 2];
    ov.w = dw * rstd * gamma[n + 3] + beta[n + 3];
    *(float4*)(out + (size_t)row * DM_ + n) = ov;
}

// ---------------------------------------------------------------------------
extern "C" void kernel_launch(void* const* d_in, const int* in_sizes, int n_in,
                              void* d_out, int out_size)
{
    const float* Q    = (const float*)d_in[0];
    const float* K    = (const float*)d_in[1];
    const float* V    = (const float*)d_in[2];
    /* d_in[3] = node_num (unused; shapes are compile-time) */
    const int*   mask = (const int*)  d_in[4];
    const float* Wq   = (const float*)d_in[5];
    const float* bq   = (const float*)d_in[6];
    const float* Wk   = (const float*)d_in[7];
    const float* bk   = (const float*)d_in[8];
    const float* Wv   = (const float*)d_in[9];
    const float* bv   = (const float*)d_in[10];
    const float* Wo   = (const float*)d_in[11];
    const float* bo   = (const float*)d_in[12];
    const float* gamma= (const float*)d_in[13];
    const float* beta = (const float*)d_in[14];
    float* out = (float*)d_out;

    dim3 thr(16, 16);

    // Projections
    gemm64<<<dim3(DM_ / 64, (B_ * LQ_) / 64), thr>>>(Q, Wq, bq, nullptr, B_ * LQ_, LQ_, 0);
    gemm64<<<dim3(DM_ / 64, (B_ * LK_) / 64), thr>>>(K, Wk, bk, nullptr, B_ * LK_, LK_, 1);
    gemm64<<<dim3(DM_ / 64, (B_ * LK_) / 64), thr>>>(V, Wv, bv, nullptr, B_ * LK_, LK_, 2);

    // Attention
    attn_kernel<<<dim3(LQ_, H_, B_), 256>>>(mask);

    // Output projection + residual
    gemm64<<<dim3(DM_ / 64, (B_ * LQ_) / 64), thr>>>(nullptr, Wo, bo, Q, B_ * LQ_, LQ_, 3);

    // LayerNorm
    layernorm_kernel<<<B_ * LQ_, 256>>>(gamma, beta, out);
}

// round 2
// speedup vs baseline: 3.9108x; 3.9108x over previous
#include <cuda_runtime.h>
#include <math.h>

#define B_  4
#define H_  16
#define LQ_ 512
#define LK_ 2048
#define DM_ 1024
#define DH_ 64

// Scratch (device globals; no runtime allocation allowed)
__device__ float g_q [(size_t)B_*H_*LQ_*DH_];   //  8 MB  [B,H,LQ,64]
__device__ float g_k [(size_t)B_*H_*LK_*DH_];   // 32 MB  [B,H,LK,64]
__device__ float g_v [(size_t)B_*H_*LK_*DH_];   // 32 MB  [B,H,LK,64]
__device__ float g_ao[(size_t)B_*LQ_*H_*DH_];   //  8 MB  [B,LQ,H*64]
__device__ float g_y [(size_t)B_*LQ_*DM_];      //  8 MB  pre-LN

// ---------------------------------------------------------------------------
// Tiled fp32 GEMM: out = X[rows,1024] @ W[1024,1024] + bias (+resid)
// Tile 128x128, BK=16, 256 threads, 8x8 micro-tile.
// ---------------------------------------------------------------------------
__global__ __launch_bounds__(256, 2)
void gemm128(const float* __restrict__ X,
             const float* __restrict__ W,
             const float* __restrict__ bias,
             const float* __restrict__ resid,
             int L, int outMode)
{
    __shared__ __align__(16) float As[16][132];   // [k][m], padded
    __shared__ __align__(16) float Bs[16][128];   // [k][n]

    const float* Xp = (outMode == 3) ? (const float*)g_ao : X;

    const int row0 = blockIdx.y * 128;
    const int col0 = blockIdx.x * 128;
    const int tx = threadIdx.x, ty = threadIdx.y;
    const int tid = ty * 16 + tx;

    float acc[8][8] = {};

    for (int k0 = 0; k0 < DM_; k0 += 16) {
        #pragma unroll
        for (int s = 0; s < 2; s++) {
            int idx = tid + s * 256;                 // 0..511
            int m  = idx >> 2;                       // 0..127
            int ks = (idx & 3) << 2;                 // 0,4,8,12
            float4 xv = *(const float4*)&Xp[(size_t)(row0 + m) * DM_ + k0 + ks];
            As[ks + 0][m] = xv.x; As[ks + 1][m] = xv.y;
            As[ks + 2][m] = xv.z; As[ks + 3][m] = xv.w;
            int kk = idx >> 5;                       // 0..15
            int ns = (idx & 31) << 2;                // 0..124
            *(float4*)&Bs[kk][ns] = *(const float4*)&W[(size_t)(k0 + kk) * DM_ + col0 + ns];
        }
        __syncthreads();

        #pragma unroll
        for (int kk = 0; kk < 16; kk++) {
            float a[8], bb[8];
            *(float4*)&a[0]  = *(const float4*)&As[kk][ty * 8];
            *(float4*)&a[4]  = *(const float4*)&As[kk][ty * 8 + 4];
            *(float4*)&bb[0] = *(const float4*)&Bs[kk][tx * 8];
            *(float4*)&bb[4] = *(const float4*)&Bs[kk][tx * 8 + 4];
            #pragma unroll
            for (int i = 0; i < 8; i++)
                #pragma unroll
                for (int j = 0; j < 8; j++)
                    acc[i][j] += a[i] * bb[j];
        }
        __syncthreads();
    }

    const int n0 = col0 + tx * 8;
    float bv[8];
    *(float4*)&bv[0] = *(const float4*)&bias[n0];
    *(float4*)&bv[4] = *(const float4*)&bias[n0 + 4];

    if (outMode == 3) {
        #pragma unroll
        for (int i = 0; i < 8; i++) {
            int row = row0 + ty * 8 + i;
            float4 r0 = *(const float4*)&resid[(size_t)row * DM_ + n0];
            float4 r1 = *(const float4*)&resid[(size_t)row * DM_ + n0 + 4];
            float4 o0, o1;
            o0.x = acc[i][0] + bv[0] + r0.x; o0.y = acc[i][1] + bv[1] + r0.y;
            o0.z = acc[i][2] + bv[2] + r0.z; o0.w = acc[i][3] + bv[3] + r0.w;
            o1.x = acc[i][4] + bv[4] + r1.x; o1.y = acc[i][5] + bv[5] + r1.y;
            o1.z = acc[i][6] + bv[6] + r1.z; o1.w = acc[i][7] + bv[7] + r1.w;
            *(float4*)&g_y[(size_t)row * DM_ + n0]     = o0;
            *(float4*)&g_y[(size_t)row * DM_ + n0 + 4] = o1;
        }
    } else {
        float* outHead = (outMode == 0) ? g_q : (outMode == 1) ? g_k : g_v;
        int h = n0 >> 6, d = n0 & 63;                 // 8 | 64, no head straddle
        #pragma unroll
        for (int i = 0; i < 8; i++) {
            int row = row0 + ty * 8 + i;
            int bq = row / L, ll = row % L;
            float* dst = outHead + (((size_t)(bq * H_ + h) * L) + ll) * DH_ + d;
            float4 o0, o1;
            o0.x = acc[i][0] + bv[0]; o0.y = acc[i][1] + bv[1];
            o0.z = acc[i][2] + bv[2]; o0.w = acc[i][3] + bv[3];
            o1.x = acc[i][4] + bv[4]; o1.y = acc[i][5] + bv[5];
            o1.z = acc[i][6] + bv[6]; o1.w = acc[i][7] + bv[7];
            *(float4*)&dst[0] = o0;
            *(float4*)&dst[4] = o1;
        }
    }
}

// ---------------------------------------------------------------------------
// Flash attention: block per (q-tile of 64, h, b). 256 threads (16x16).
// Online softmax, K/V tiles of 64 in smem, 4x4 register micro-tiles.
// smem stride 68 floats: float4-aligned, bank-conflict-free patterns.
// ---------------------------------------------------------------------------
#define FA_SMEM ((4 * 64 * 68 + 64) * 4)

__global__ __launch_bounds__(256, 2)
void flash_attn(const int* __restrict__ mask)
{
    extern __shared__ float smf[];
    float* Qs  = smf;                 // [64][68]  q-major, d contiguous
    float* Ks  = Qs + 64 * 68;        // [64][68]  k-major, d contiguous
    float* Vs  = Ks + 64 * 68;        // [64][68]  k-major, dv contiguous
    float* Ps  = Vs + 64 * 68;        // [64][68]  q-major, k contiguous
    float* msk = Ps + 64 * 68;        // [64]

    const int q0 = blockIdx.x * 64, h = blockIdx.y, b = blockIdx.z;
    const int tx = threadIdx.x, ty = threadIdx.y;
    const int tid = ty * 16 + tx;

    const float* qbase = g_q + ((size_t)(b * H_ + h) * LQ_ + q0) * DH_;
    const float* kbase = g_k + (size_t)(b * H_ + h) * LK_ * DH_;
    const float* vbase = g_v + (size_t)(b * H_ + h) * LK_ * DH_;

    #pragma unroll
    for (int s = 0; s < 4; s++) {
        int idx = tid + s * 256;
        int r = idx >> 4, dseg = (idx & 15) << 2;
        *(float4*)&Qs[r * 68 + dseg] = *(const float4*)&qbase[(size_t)r * DH_ + dseg];
    }

    float m[4], l[4], o[4][4];
    #pragma unroll
    for (int i = 0; i < 4; i++) {
        m[i] = -1e30f; l[i] = 0.f;
        #pragma unroll
        for (int j = 0; j < 4; j++) o[i][j] = 0.f;
    }

    for (int t = 0; t < LK_ / 64; t++) {
        const int k0 = t * 64;
        __syncthreads();   // previous O-GEMM done reading Vs/Ps before overwrite
        #pragma unroll
        for (int s = 0; s < 4; s++) {
            int idx = tid + s * 256;
            int r = idx >> 4, dseg = (idx & 15) << 2;
            *(float4*)&Ks[r * 68 + dseg] = *(const float4*)&kbase[(size_t)(k0 + r) * DH_ + dseg];
            *(float4*)&Vs[r * 68 + dseg] = *(const float4*)&vbase[(size_t)(k0 + r) * DH_ + dseg];
        }
        if (tid < 64) msk[tid] = (mask[b * LK_ + k0 + tid] == 0) ? -1e30f : 0.0f;
        __syncthreads();

        // ---- S = Q Kt  (q rows: ty*4+i, k cols: tx+16j) ----
        float sc[4][4] = {};
        #pragma unroll
        for (int d4 = 0; d4 < DH_; d4 += 4) {
            float4 aq[4], bk[4];
            #pragma unroll
            for (int i = 0; i < 4; i++) aq[i] = *(const float4*)&Qs[(ty * 4 + i) * 68 + d4];
            #pragma unroll
            for (int j = 0; j < 4; j++) bk[j] = *(const float4*)&Ks[(tx + 16 * j) * 68 + d4];
            #pragma unroll
            for (int i = 0; i < 4; i++)
                #pragma unroll
                for (int j = 0; j < 4; j++)
                    sc[i][j] += aq[i].x * bk[j].x + aq[i].y * bk[j].y +
                                aq[i].z * bk[j].z + aq[i].w * bk[j].w;
        }

        // ---- online softmax (row reductions over 16 tx lanes) ----
        const float scl = 0.125f;   // 1/sqrt(64)
        #pragma unroll
        for (int i = 0; i < 4; i++) {
            float rmax = -1e30f;
            #pragma unroll
            for (int j = 0; j < 4; j++) {
                sc[i][j] = sc[i][j] * scl + msk[tx + 16 * j];
                rmax = fmaxf(rmax, sc[i][j]);
            }
            #pragma unroll
            for (int off = 8; off > 0; off >>= 1)
                rmax = fmaxf(rmax, __shfl_xor_sync(0xffffffffu, rmax, off, 16));
            float mnew = fmaxf(m[i], rmax);
            float corr = __expf(m[i] - mnew);
            float rsum = 0.f;
            #pragma unroll
            for (int j = 0; j < 4; j++) {
                float p = __expf(sc[i][j] - mnew);
                sc[i][j] = p;
                rsum += p;
            }
            #pragma unroll
            for (int off = 8; off > 0; off >>= 1)
                rsum += __shfl_xor_sync(0xffffffffu, rsum, off, 16);
            l[i] = l[i] * corr + rsum;
            m[i] = mnew;
            #pragma unroll
            for (int j = 0; j < 4; j++) {
                o[i][j] *= corr;
                Ps[(ty * 4 + i) * 68 + tx + 16 * j] = sc[i][j];
            }
        }
        __syncthreads();

        // ---- O += P V  (q rows: ty*4+i, dv cols: tx*4+j) ----
        #pragma unroll 8
        for (int kk = 0; kk < 64; kk++) {
            float4 vv = *(const float4*)&Vs[kk * 68 + tx * 4];
            float p0 = Ps[(ty * 4 + 0) * 68 + kk];
            float p1 = Ps[(ty * 4 + 1) * 68 + kk];
            float p2 = Ps[(ty * 4 + 2) * 68 + kk];
            float p3 = Ps[(ty * 4 + 3) * 68 + kk];
            o[0][0] += p0 * vv.x; o[0][1] += p0 * vv.y; o[0][2] += p0 * vv.z; o[0][3] += p0 * vv.w;
            o[1][0] += p1 * vv.x; o[1][1] += p1 * vv.y; o[1][2] += p1 * vv.z; o[1][3] += p1 * vv.w;
            o[2][0] += p2 * vv.x; o[2][1] += p2 * vv.y; o[2][2] += p2 * vv.z; o[2][3] += p2 * vv.w;
            o[3][0] += p3 * vv.x; o[3][1] += p3 * vv.y; o[3][2] += p3 * vv.z; o[3][3] += p3 * vv.w;
        }
    }

    #pragma unroll
    for (int i = 0; i < 4; i++) {
        float inv = 1.0f / l[i];
        int q = q0 + ty * 4 + i;
        float4 ov;
        ov.x = o[i][0] * inv; ov.y = o[i][1] * inv;
        ov.z = o[i][2] * inv; ov.w = o[i][3] * inv;
        *(float4*)&g_ao[((size_t)(b * LQ_ + q) * H_ + h) * DH_ + tx * 4] = ov;
    }
}

// ---------------------------------------------------------------------------
// LayerNorm per row of g_y, write final output
// ---------------------------------------------------------------------------
__global__ void layernorm_kernel(const float* __restrict__ gamma,
                                 const float* __restrict__ beta,
                                 float* __restrict__ out)
{
    const int row = blockIdx.x;
    const int tid = threadIdx.x;
    __shared__ float red[256];

    const float* yr = g_y + (size_t)row * DM_;
    float4 xv = *(const float4*)(yr + tid * 4);

    float s = xv.x + xv.y + xv.z + xv.w;
    red[tid] = s; __syncthreads();
    #pragma unroll
    for (int st = 128; st > 0; st >>= 1) {
        if (tid < st) red[tid] += red[tid + st];
        __syncthreads();
    }
    float mean = red[0] * (1.0f / DM_);
    __syncthreads();

    float dx = xv.x - mean, dy = xv.y - mean, dz = xv.z - mean, dw = xv.w - mean;
    float sq = dx * dx + dy * dy + dz * dz + dw * dw;
    red[tid] = sq; __syncthreads();
    #pragma unroll
    for (int st = 128; st > 0; st >>= 1) {
        if (tid < st) red[tid] += red[tid + st];
        __syncthreads();
    }
    float rstd = rsqrtf(red[0] * (1.0f / DM_) + 1e-5f);

    int n = tid * 4;
    float4 ov;
    ov.x = dx * rstd * gamma[n]     + beta[n];
    ov.y = dy * rstd * gamma[n + 1] + beta[n + 1];
    ov.z = dz * rstd * gamma[n + 2] + beta[n + 2];
    ov.w = dw * rstd * gamma[n + 3] + beta[n + 3];
    *(float4*)(out + (size_t)row * DM_ + n) = ov;
}

// ---------------------------------------------------------------------------
extern "C" void kernel_launch(void* const* d_in, const int* in_sizes, int n_in,
                              void* d_out, int out_size)
{
    const float* Q    = (const float*)d_in[0];
    const float* K    = (const float*)d_in[1];
    const float* V    = (const float*)d_in[2];
    /* d_in[3] = node_num (unused; compile-time shapes) */
    const int*   mask = (const int*)  d_in[4];
    const float* Wq   = (const float*)d_in[5];
    const float* bq   = (const float*)d_in[6];
    const float* Wk   = (const float*)d_in[7];
    const float* bk   = (const float*)d_in[8];
    const float* Wv   = (const float*)d_in[9];
    const float* bv   = (const float*)d_in[10];
    const float* Wo   = (const float*)d_in[11];
    const float* bo   = (const float*)d_in[12];
    const float* gamma= (const float*)d_in[13];
    const float* beta = (const float*)d_in[14];
    float* out = (float*)d_out;

    cudaFuncSetAttribute(flash_attn, cudaFuncAttributeMaxDynamicSharedMemorySize, FA_SMEM);

    dim3 thr(16, 16);

    // Projections
    gemm128<<<dim3(DM_ / 128, (B_ * LQ_) / 128), thr>>>(Q, Wq, bq, nullptr, LQ_, 0);
    gemm128<<<dim3(DM_ / 128, (B_ * LK_) / 128), thr>>>(K, Wk, bk, nullptr, LK_, 1);
    gemm128<<<dim3(DM_ / 128, (B_ * LK_) / 128), thr>>>(V, Wv, bv, nullptr, LK_, 2);

    // Attention (flash, 64-query tiles)
    flash_attn<<<dim3(LQ_ / 64, H_, B_), thr, FA_SMEM>>>(mask);

    // Output projection + residual
    gemm128<<<dim3(DM_ / 128, (B_ * LQ_) / 128), thr>>>(nullptr, Wo, bo, Q, LQ_, 3);

    // LayerNorm
    layernorm_kernel<<<B_ * LQ_, 256>>>(gamma, beta, out);
}

// round 3
// speedup vs baseline: 4.6999x; 1.2018x over previous
#include <cuda_runtime.h>
#include <math.h>
#include <stdint.h>

#define B_  4
#define H_  16
#define LQ_ 512
#define LK_ 2048
#define DM_ 1024
#define DH_ 64

// Scratch (device globals; no runtime allocation allowed)
__device__ float g_q [(size_t)B_*H_*LQ_*DH_];   //  8 MB  [B,H,LQ,64]
__device__ float g_k [(size_t)B_*H_*LK_*DH_];   // 32 MB  [B,H,LK,64]
__device__ float g_v [(size_t)B_*H_*LK_*DH_];   // 32 MB  [B,H,LK,64]
__device__ float g_ao[(size_t)B_*LQ_*H_*DH_];   //  8 MB  [B,LQ,H*64]
__device__ float g_y [(size_t)B_*LQ_*DM_];      //  8 MB  pre-LN

// ---------------------------------------------------------------------------
// tf32 helpers
// ---------------------------------------------------------------------------
__device__ __forceinline__ uint32_t f2tf32(float x) {
    uint32_t r;
    asm("cvt.rna.tf32.f32 %0, %1;" : "=r"(r) : "f"(x));
    return r;
}

__device__ __forceinline__ void mma_tf32(float c[4],
                                         uint32_t a0, uint32_t a1, uint32_t a2, uint32_t a3,
                                         uint32_t b0, uint32_t b1)
{
    asm volatile(
        "mma.sync.aligned.m16n8k8.row.col.f32.tf32.tf32.f32 "
        "{%0,%1,%2,%3}, {%4,%5,%6,%7}, {%8,%9}, {%0,%1,%2,%3};"
        : "+f"(c[0]), "+f"(c[1]), "+f"(c[2]), "+f"(c[3])
        : "r"(a0), "r"(a1), "r"(a2), "r"(a3), "r"(b0), "r"(b1));
}

// ---------------------------------------------------------------------------
// tf32 3-pass GEMM: out = X[rows,1024] @ W[1024,1024] + bias (+resid)
// CTA tile 128x128, BK=32, 256 threads (8 warps, 2x4), warp tile 64x32.
// Split: hi = tf32(x), lo = tf32(x - hi);  D += Ah*Bh + Ah*Bl + Al*Bh.
// Smem strides: A stride 36 (bank = lane, conflict-free), B stride 136.
// ---------------------------------------------------------------------------
#define GS_XH 0
#define GS_XL (128 * 36)
#define GS_WH (2 * 128 * 36)
#define GS_WL (2 * 128 * 36 + 32 * 136)
#define GEMM_SMEM ((2 * 128 * 36 + 2 * 32 * 136) * 4)

__global__ __launch_bounds__(256)
void gemm_tf32(const float* __restrict__ X,
               const float* __restrict__ W,
               const float* __restrict__ bias,
               const float* __restrict__ resid,
               int L, int outMode)
{
    extern __shared__ uint32_t sm[];
    uint32_t* Xh = sm + GS_XH;
    uint32_t* Xl = sm + GS_XL;
    uint32_t* Wh = sm + GS_WH;
    uint32_t* Wl = sm + GS_WL;

    const float* Xp = (outMode == 3) ? (const float*)g_ao : X;

    const int row0 = blockIdx.y * 128;
    const int col0 = blockIdx.x * 128;
    const int tid  = threadIdx.x;
    const int lane = tid & 31;
    const int w    = tid >> 5;
    const int wm   = (w >> 2) * 64;     // 0,64
    const int wn   = (w & 3) * 32;      // 0,32,64,96
    const int grp  = lane >> 2;         // 0..7
    const int tg   = lane & 3;          // 0..3

    float acc[4][4][4] = {};

    // global-load assignments
    const int xm = tid >> 1;                 // 0..127
    const int xk = (tid & 1) * 16;           // 0 or 16
    const int wk = tid >> 3;                 // 0..31
    const int wn4 = (tid & 7);               // 0..7

    for (int k0 = 0; k0 < DM_; k0 += 32) {
        // ---- load + split X tile [128 x 32] ----
        #pragma unroll
        for (int i = 0; i < 4; i++) {
            int k = xk + i * 4;
            float4 xv = *(const float4*)&Xp[(size_t)(row0 + xm) * DM_ + k0 + k];
            uint32_t h0 = f2tf32(xv.x), h1 = f2tf32(xv.y), h2 = f2tf32(xv.z), h3 = f2tf32(xv.w);
            uint4 hv = {h0, h1, h2, h3};
            uint4 lv = {f2tf32(xv.x - __uint_as_float(h0)),
                        f2tf32(xv.y - __uint_as_float(h1)),
                        f2tf32(xv.z - __uint_as_float(h2)),
                        f2tf32(xv.w - __uint_as_float(h3))};
            *(uint4*)&Xh[xm * 36 + k] = hv;
            *(uint4*)&Xl[xm * 36 + k] = lv;
        }
        // ---- load + split W tile [32 x 128] ----
        #pragma unroll
        for (int i = 0; i < 4; i++) {
            int n = (wn4 + i * 8) * 4;
            float4 wv = *(const float4*)&W[(size_t)(k0 + wk) * DM_ + col0 + n];
            uint32_t h0 = f2tf32(wv.x), h1 = f2tf32(wv.y), h2 = f2tf32(wv.z), h3 = f2tf32(wv.w);
            uint4 hv = {h0, h1, h2, h3};
            uint4 lv = {f2tf32(wv.x - __uint_as_float(h0)),
                        f2tf32(wv.y - __uint_as_float(h1)),
                        f2tf32(wv.z - __uint_as_float(h2)),
                        f2tf32(wv.w - __uint_as_float(h3))};
            *(uint4*)&Wh[wk * 136 + n] = hv;
            *(uint4*)&Wl[wk * 136 + n] = lv;
        }
        __syncthreads();

        #pragma unroll
        for (int kt = 0; kt < 4; kt++) {
            const int kb = kt * 8;
            // B fragments for 4 n-tiles (hi & lo)
            uint32_t bh[4][2], bl[4][2];
            #pragma unroll
            for (int n = 0; n < 4; n++) {
                int cidx = wn + n * 8 + grp;
                int ridx = kb + tg;
                bh[n][0] = Wh[ridx * 136 + cidx];
                bh[n][1] = Wh[(ridx + 4) * 136 + cidx];
                bl[n][0] = Wl[ridx * 136 + cidx];
                bl[n][1] = Wl[(ridx + 4) * 136 + cidx];
            }
            #pragma unroll
            for (int m = 0; m < 4; m++) {
                int r = wm + m * 16 + grp;
                int c = kb + tg;
                uint32_t ah0 = Xh[r * 36 + c];
                uint32_t ah1 = Xh[(r + 8) * 36 + c];
                uint32_t ah2 = Xh[r * 36 + c + 4];
                uint32_t ah3 = Xh[(r + 8) * 36 + c + 4];
                uint32_t al0 = Xl[r * 36 + c];
                uint32_t al1 = Xl[(r + 8) * 36 + c];
                uint32_t al2 = Xl[r * 36 + c + 4];
                uint32_t al3 = Xl[(r + 8) * 36 + c + 4];
                #pragma unroll
                for (int n = 0; n < 4; n++) {
                    mma_tf32(acc[m][n], ah0, ah1, ah2, ah3, bh[n][0], bh[n][1]);
                    mma_tf32(acc[m][n], ah0, ah1, ah2, ah3, bl[n][0], bl[n][1]);
                    mma_tf32(acc[m][n], al0, al1, al2, al3, bh[n][0], bh[n][1]);
                }
            }
        }
        __syncthreads();
    }

    // ---- epilogue ----
    #pragma unroll
    for (int n = 0; n < 4; n++) {
        const int gc = col0 + wn + n * 8 + tg * 2;
        const float b0 = bias[gc], b1 = bias[gc + 1];
        #pragma unroll
        for (int m = 0; m < 4; m++) {
            int r0 = row0 + wm + m * 16 + grp;
            int r1 = r0 + 8;
            float v00 = acc[m][n][0] + b0, v01 = acc[m][n][1] + b1;
            float v10 = acc[m][n][2] + b0, v11 = acc[m][n][3] + b1;
            if (outMode == 3) {
                float2 rr0 = *(const float2*)&resid[(size_t)r0 * DM_ + gc];
                float2 rr1 = *(const float2*)&resid[(size_t)r1 * DM_ + gc];
                float2 o0 = {v00 + rr0.x, v01 + rr0.y};
                float2 o1 = {v10 + rr1.x, v11 + rr1.y};
                *(float2*)&g_y[(size_t)r0 * DM_ + gc] = o0;
                *(float2*)&g_y[(size_t)r1 * DM_ + gc] = o1;
            } else {
                float* outHead = (outMode == 0) ? g_q : (outMode == 1) ? g_k : g_v;
                int h = gc >> 6, d = gc & 63;
                int b0i = r0 / L, l0 = r0 % L;
                int b1i = r1 / L, l1 = r1 % L;
                float2 o0 = {v00, v01};
                float2 o1 = {v10, v11};
                *(float2*)&outHead[(((size_t)(b0i * H_ + h) * L) + l0) * DH_ + d] = o0;
                *(float2*)&outHead[(((size_t)(b1i * H_ + h) * L) + l1) * DH_ + d] = o1;
            }
        }
    }
}

// ---------------------------------------------------------------------------
// Flash attention: block per (q-tile of 64, h, b). 256 threads (16x16).
// ---------------------------------------------------------------------------
#define FA_SMEM ((4 * 64 * 68 + 64) * 4)

__global__ __launch_bounds__(256, 2)
void flash_attn(const int* __restrict__ mask)
{
    extern __shared__ float smf[];
    float* Qs  = smf;                 // [64][68]
    float* Ks  = Qs + 64 * 68;        // [64][68]
    float* Vs  = Ks + 64 * 68;        // [64][68]
    float* Ps  = Vs + 64 * 68;        // [64][68]
    float* msk = Ps + 64 * 68;        // [64]

    const int q0 = blockIdx.x * 64, h = blockIdx.y, b = blockIdx.z;
    const int tx = threadIdx.x, ty = threadIdx.y;
    const int tid = ty * 16 + tx;

    const float* qbase = g_q + ((size_t)(b * H_ + h) * LQ_ + q0) * DH_;
    const float* kbase = g_k + (size_t)(b * H_ + h) * LK_ * DH_;
    const float* vbase = g_v + (size_t)(b * H_ + h) * LK_ * DH_;

    #pragma unroll
    for (int s = 0; s < 4; s++) {
        int idx = tid + s * 256;
        int r = idx >> 4, dseg = (idx & 15) << 2;
        *(float4*)&Qs[r * 68 + dseg] = *(const float4*)&qbase[(size_t)r * DH_ + dseg];
    }

    float m[4], l[4], o[4][4];
    #pragma unroll
    for (int i = 0; i < 4; i++) {
        m[i] = -1e30f; l[i] = 0.f;
        #pragma unroll
        for (int j = 0; j < 4; j++) o[i][j] = 0.f;
    }

    for (int t = 0; t < LK_ / 64; t++) {
        const int k0 = t * 64;
        __syncthreads();
        #pragma unroll
        for (int s = 0; s < 4; s++) {
            int idx = tid + s * 256;
            int r = idx >> 4, dseg = (idx & 15) << 2;
            *(float4*)&Ks[r * 68 + dseg] = *(const float4*)&kbase[(size_t)(k0 + r) * DH_ + dseg];
            *(float4*)&Vs[r * 68 + dseg] = *(const float4*)&vbase[(size_t)(k0 + r) * DH_ + dseg];
        }
        if (tid < 64) msk[tid] = (mask[b * LK_ + k0 + tid] == 0) ? -1e30f : 0.0f;
        __syncthreads();

        float sc[4][4] = {};
        #pragma unroll
        for (int d4 = 0; d4 < DH_; d4 += 4) {
            float4 aq[4], bk[4];
            #pragma unroll
            for (int i = 0; i < 4; i++) aq[i] = *(const float4*)&Qs[(ty * 4 + i) * 68 + d4];
            #pragma unroll
            for (int j = 0; j < 4; j++) bk[j] = *(const float4*)&Ks[(tx + 16 * j) * 68 + d4];
            #pragma unroll
            for (int i = 0; i < 4; i++)
                #pragma unroll
                for (int j = 0; j < 4; j++)
                    sc[i][j] += aq[i].x * bk[j].x + aq[i].y * bk[j].y +
                                aq[i].z * bk[j].z + aq[i].w * bk[j].w;
        }

        const float scl = 0.125f;
        #pragma unroll
        for (int i = 0; i < 4; i++) {
            float rmax = -1e30f;
            #pragma unroll
            for (int j = 0; j < 4; j++) {
                sc[i][j] = sc[i][j] * scl + msk[tx + 16 * j];
                rmax = fmaxf(rmax, sc[i][j]);
            }
            #pragma unroll
            for (int off = 8; off > 0; off >>= 1)
                rmax = fmaxf(rmax, __shfl_xor_sync(0xffffffffu, rmax, off, 16));
            float mnew = fmaxf(m[i], rmax);
            float corr = __expf(m[i] - mnew);
            float rsum = 0.f;
            #pragma unroll
            for (int j = 0; j < 4; j++) {
                float p = __expf(sc[i][j] - mnew);
                sc[i][j] = p;
                rsum += p;
            }
            #pragma unroll
            for (int off = 8; off > 0; off >>= 1)
                rsum += __shfl_xor_sync(0xffffffffu, rsum, off, 16);
            l[i] = l[i] * corr + rsum;
            m[i] = mnew;
            #pragma unroll
            for (int j = 0; j < 4; j++) {
                o[i][j] *= corr;
                Ps[(ty * 4 + i) * 68 + tx + 16 * j] = sc[i][j];
            }
        }
        __syncthreads();

        #pragma unroll 8
        for (int kk = 0; kk < 64; kk++) {
            float4 vv = *(const float4*)&Vs[kk * 68 + tx * 4];
            float p0 = Ps[(ty * 4 + 0) * 68 + kk];
            float p1 = Ps[(ty * 4 + 1) * 68 + kk];
            float p2 = Ps[(ty * 4 + 2) * 68 + kk];
            float p3 = Ps[(ty * 4 + 3) * 68 + kk];
            o[0][0] += p0 * vv.x; o[0][1] += p0 * vv.y; o[0][2] += p0 * vv.z; o[0][3] += p0 * vv.w;
            o[1][0] += p1 * vv.x; o[1][1] += p1 * vv.y; o[1][2] += p1 * vv.z; o[1][3] += p1 * vv.w;
            o[2][0] += p2 * vv.x; o[2][1] += p2 * vv.y; o[2][2] += p2 * vv.z; o[2][3] += p2 * vv.w;
            o[3][0] += p3 * vv.x; o[3][1] += p3 * vv.y; o[3][2] += p3 * vv.z; o[3][3] += p3 * vv.w;
        }
    }

    #pragma unroll
    for (int i = 0; i < 4; i++) {
        float inv = 1.0f / l[i];
        int q = q0 + ty * 4 + i;
        float4 ov;
        ov.x = o[i][0] * inv; ov.y = o[i][1] * inv;
        ov.z = o[i][2] * inv; ov.w = o[i][3] * inv;
        *(float4*)&g_ao[((size_t)(b * LQ_ + q) * H_ + h) * DH_ + tx * 4] = ov;
    }
}

// ---------------------------------------------------------------------------
// LayerNorm per row of g_y, write final output
// ---------------------------------------------------------------------------
__global__ void layernorm_kernel(const float* __restrict__ gamma,
                                 const float* __restrict__ beta,
                                 float* __restrict__ out)
{
    const int row = blockIdx.x;
    const int tid = threadIdx.x;
    __shared__ float red[256];

    const float* yr = g_y + (size_t)row * DM_;
    float4 xv = *(const float4*)(yr + tid * 4);

    float s = xv.x + xv.y + xv.z + xv.w;
    red[tid] = s; __syncthreads();
    #pragma unroll
    for (int st = 128; st > 0; st >>= 1) {
        if (tid < st) red[tid] += red[tid + st];
        __syncthreads();
    }
    float mean = red[0] * (1.0f / DM_);
    __syncthreads();

    float dx = xv.x - mean, dy = xv.y - mean, dz = xv.z - mean, dw = xv.w - mean;
    float sq = dx * dx + dy * dy + dz * dz + dw * dw;
    red[tid] = sq; __syncthreads();
    #pragma unroll
    for (int st = 128; st > 0; st >>= 1) {
        if (tid < st) red[tid] += red[tid + st];
        __syncthreads();
    }
    float rstd = rsqrtf(red[0] * (1.0f / DM_) + 1e-5f);

    int n = tid * 4;
    float4 ov;
    ov.x = dx * rstd * gamma[n]     + beta[n];
    ov.y = dy * rstd * gamma[n + 1] + beta[n + 1];
    ov.z = dz * rstd * gamma[n + 2] + beta[n + 2];
    ov.w = dw * rstd * gamma[n + 3] + beta[n + 3];
    *(float4*)(out + (size_t)row * DM_ + n) = ov;
}

// ---------------------------------------------------------------------------
extern "C" void kernel_launch(void* const* d_in, const int* in_sizes, int n_in,
                              void* d_out, int out_size)
{
    const float* Q    = (const float*)d_in[0];
    const float* K    = (const float*)d_in[1];
    const float* V    = (const float*)d_in[2];
    /* d_in[3] = node_num (unused; compile-time shapes) */
    const int*   mask = (const int*)  d_in[4];
    const float* Wq   = (const float*)d_in[5];
    const float* bq   = (const float*)d_in[6];
    const float* Wk   = (const float*)d_in[7];
    const float* bk   = (const float*)d_in[8];
    const float* Wv   = (const float*)d_in[9];
    const float* bv   = (const float*)d_in[10];
    const float* Wo   = (const float*)d_in[11];
    const float* bo   = (const float*)d_in[12];
    const float* gamma= (const float*)d_in[13];
    const float* beta = (const float*)d_in[14];
    float* out = (float*)d_out;

    cudaFuncSetAttribute(gemm_tf32,  cudaFuncAttributeMaxDynamicSharedMemorySize, GEMM_SMEM);
    cudaFuncSetAttribute(flash_attn, cudaFuncAttributeMaxDynamicSharedMemorySize, FA_SMEM);

    // Projections (tf32 tensor-core, 3-pass split)
    gemm_tf32<<<dim3(DM_ / 128, (B_ * LQ_) / 128), 256, GEMM_SMEM>>>(Q, Wq, bq, nullptr, LQ_, 0);
    gemm_tf32<<<dim3(DM_ / 128, (B_ * LK_) / 128), 256, GEMM_SMEM>>>(K, Wk, bk, nullptr, LK_, 1);
    gemm_tf32<<<dim3(DM_ / 128, (B_ * LK_) / 128), 256, GEMM_SMEM>>>(V, Wv, bv, nullptr, LK_, 2);

    // Attention (flash, 64-query tiles)
    flash_attn<<<dim3(LQ_ / 64, H_, B_), dim3(16, 16), FA_SMEM>>>(mask);

    // Output projection + residual
    gemm_tf32<<<dim3(DM_ / 128, (B_ * LQ_) / 128), 256, GEMM_SMEM>>>(nullptr, Wo, bo, Q, LQ_, 3);

    // LayerNorm
    layernorm_kernel<<<B_ * LQ_, 256>>>(gamma, beta, out);
}

// round 4
// speedup vs baseline: 7.5945x; 1.6159x over previous
#include <cuda_runtime.h>
#include <math.h>
#include <stdint.h>

#define B_  4
#define H_  16
#define LQ_ 512
#define LK_ 2048
#define DM_ 1024
#define DH_ 64

// Scratch (device globals; no runtime allocation allowed)
__device__ float g_q [(size_t)B_*H_*LQ_*DH_];   //  [B,H,LQ,64]
__device__ float g_k [(size_t)B_*H_*LK_*DH_];   //  [B,H,LK,64]
__device__ float g_v [(size_t)B_*H_*LK_*DH_];   //  [B,H,LK,64]
__device__ float g_ao[(size_t)B_*LQ_*H_*DH_];   //  [B,LQ,H*64]
__device__ float g_y [(size_t)B_*LQ_*DM_];      //  pre-LN

// ---------------------------------------------------------------------------
// bf16 helpers: pack two floats (even->low, odd->high), hi/lo split
// ---------------------------------------------------------------------------
__device__ __forceinline__ uint32_t packbf(float e, float o) {
    uint32_t r;
    asm("cvt.rn.bf16x2.f32 %0, %1, %2;" : "=r"(r) : "f"(o), "f"(e));
    return r;
}
__device__ __forceinline__ float lo16f(uint32_t h) { return __uint_as_float(h << 16); }
__device__ __forceinline__ float hi16f(uint32_t h) { return __uint_as_float(h & 0xffff0000u); }

__device__ __forceinline__ void split2(float x, float y, uint32_t& hi, uint32_t& lo) {
    hi = packbf(x, y);
    lo = packbf(x - lo16f(hi), y - hi16f(hi));
}

__device__ __forceinline__ void mma_bf16(float c[4],
                                         uint32_t a0, uint32_t a1, uint32_t a2, uint32_t a3,
                                         uint32_t b0, uint32_t b1)
{
    asm volatile(
        "mma.sync.aligned.m16n8k16.row.col.f32.bf16.bf16.f32 "
        "{%0,%1,%2,%3}, {%4,%5,%6,%7}, {%8,%9}, {%0,%1,%2,%3};"
        : "+f"(c[0]), "+f"(c[1]), "+f"(c[2]), "+f"(c[3])
        : "r"(a0), "r"(a1), "r"(a2), "r"(a3), "r"(b0), "r"(b1));
}

// ---------------------------------------------------------------------------
// bf16 3-pass GEMM: out = X[rows,1024] @ W[1024,1024] + bias (+resid)
// CTA 128x128, BK=32, 256 threads (8 warps 2x4), warp tile 64x32.
// Smem (uint32, each = bf16x2 along k):
//   X: [128 rows][16 kpairs] stride 20   W: [16 kpairs][128 n] stride 136
// ---------------------------------------------------------------------------
#define GS_XH 0
#define GS_XL (128 * 20)
#define GS_WH (2 * 128 * 20)
#define GS_WL (2 * 128 * 20 + 16 * 136)
#define GEMM_SMEM ((2 * 128 * 20 + 2 * 16 * 136) * 4)

__global__ __launch_bounds__(256)
void gemm_bf16(const float* __restrict__ X,
               const float* __restrict__ W,
               const float* __restrict__ bias,
               const float* __restrict__ resid,
               int L, int outMode)
{
    extern __shared__ uint32_t sm[];
    uint32_t* Xh = sm + GS_XH;
    uint32_t* Xl = sm + GS_XL;
    uint32_t* Wh = sm + GS_WH;
    uint32_t* Wl = sm + GS_WL;

    const float* Xp = (outMode == 3) ? (const float*)g_ao : X;

    const int row0 = blockIdx.y * 128;
    const int col0 = blockIdx.x * 128;
    const int tid  = threadIdx.x;
    const int lane = tid & 31;
    const int w    = tid >> 5;
    const int wm   = (w >> 2) * 64;     // 0,64
    const int wn   = (w & 3) * 32;      // 0,32,64,96
    const int grp  = lane >> 2;         // 0..7
    const int tg   = lane & 3;          // 0..3

    float acc[4][4][4] = {};

    const int xm = tid >> 1;            // 0..127
    const int xk = (tid & 1) * 16;      // 0 or 16
    const int wkp = tid >> 4;           // 0..15 kpair
    const int wn0 = (tid & 15) * 8;     // 0..120

    for (int k0 = 0; k0 < DM_; k0 += 32) {
        // ---- X tile [128 x 32] -> hi/lo kpairs ----
        #pragma unroll
        for (int i = 0; i < 4; i++) {
            int k = xk + i * 4;
            float4 xv = *(const float4*)&Xp[(size_t)(row0 + xm) * DM_ + k0 + k];
            uint2 hv, lv;
            split2(xv.x, xv.y, hv.x, lv.x);
            split2(xv.z, xv.w, hv.y, lv.y);
            *(uint2*)&Xh[xm * 20 + (k >> 1)] = hv;
            *(uint2*)&Xl[xm * 20 + (k >> 1)] = lv;
        }
        // ---- W tile [32 x 128]: pair across two k rows ----
        {
            const float* w0 = &W[(size_t)(k0 + 2 * wkp) * DM_ + col0 + wn0];
            const float* w1 = w0 + DM_;
            float4 a0 = *(const float4*)w0, a1 = *(const float4*)(w0 + 4);
            float4 b0v = *(const float4*)w1, b1v = *(const float4*)(w1 + 4);
            uint4 hA, lA, hB, lB;
            split2(a0.x, b0v.x, hA.x, lA.x);
            split2(a0.y, b0v.y, hA.y, lA.y);
            split2(a0.z, b0v.z, hA.z, lA.z);
            split2(a0.w, b0v.w, hA.w, lA.w);
            split2(a1.x, b1v.x, hB.x, lB.x);
            split2(a1.y, b1v.y, hB.y, lB.y);
            split2(a1.z, b1v.z, hB.z, lB.z);
            split2(a1.w, b1v.w, hB.w, lB.w);
            *(uint4*)&Wh[wkp * 136 + wn0]     = hA;
            *(uint4*)&Wh[wkp * 136 + wn0 + 4] = hB;
            *(uint4*)&Wl[wkp * 136 + wn0]     = lA;
            *(uint4*)&Wl[wkp * 136 + wn0 + 4] = lB;
        }
        __syncthreads();

        #pragma unroll
        for (int kt = 0; kt < 2; kt++) {
            const int kb = kt * 8;
            uint32_t bh[4][2], bl[4][2];
            #pragma unroll
            for (int nt = 0; nt < 4; nt++) {
                int cc = wn + nt * 8 + grp;
                bh[nt][0] = Wh[(kb + tg) * 136 + cc];
                bh[nt][1] = Wh[(kb + tg + 4) * 136 + cc];
                bl[nt][0] = Wl[(kb + tg) * 136 + cc];
                bl[nt][1] = Wl[(kb + tg + 4) * 136 + cc];
            }
            #pragma unroll
            for (int m = 0; m < 4; m++) {
                int r = wm + m * 16 + grp;
                uint32_t ah0 = Xh[r * 20 + kb + tg];
                uint32_t ah1 = Xh[(r + 8) * 20 + kb + tg];
                uint32_t ah2 = Xh[r * 20 + kb + tg + 4];
                uint32_t ah3 = Xh[(r + 8) * 20 + kb + tg + 4];
                uint32_t al0 = Xl[r * 20 + kb + tg];
                uint32_t al1 = Xl[(r + 8) * 20 + kb + tg];
                uint32_t al2 = Xl[r * 20 + kb + tg + 4];
                uint32_t al3 = Xl[(r + 8) * 20 + kb + tg + 4];
                #pragma unroll
                for (int nt = 0; nt < 4; nt++) {
                    mma_bf16(acc[m][nt], ah0, ah1, ah2, ah3, bh[nt][0], bh[nt][1]);
                    mma_bf16(acc[m][nt], ah0, ah1, ah2, ah3, bl[nt][0], bl[nt][1]);
                    mma_bf16(acc[m][nt], al0, al1, al2, al3, bh[nt][0], bh[nt][1]);
                }
            }
        }
        __syncthreads();
    }

    // ---- epilogue ----
    #pragma unroll
    for (int nt = 0; nt < 4; nt++) {
        const int gc = col0 + wn + nt * 8 + tg * 2;
        const float b0 = bias[gc], b1 = bias[gc + 1];
        #pragma unroll
        for (int m = 0; m < 4; m++) {
            int r0 = row0 + wm + m * 16 + grp;
            int r1 = r0 + 8;
            float v00 = acc[m][nt][0] + b0, v01 = acc[m][nt][1] + b1;
            float v10 = acc[m][nt][2] + b0, v11 = acc[m][nt][3] + b1;
            if (outMode == 3) {
                float2 rr0 = *(const float2*)&resid[(size_t)r0 * DM_ + gc];
                float2 rr1 = *(const float2*)&resid[(size_t)r1 * DM_ + gc];
                float2 o0 = {v00 + rr0.x, v01 + rr0.y};
                float2 o1 = {v10 + rr1.x, v11 + rr1.y};
                *(float2*)&g_y[(size_t)r0 * DM_ + gc] = o0;
                *(float2*)&g_y[(size_t)r1 * DM_ + gc] = o1;
            } else {
                float* outHead = (outMode == 0) ? g_q : (outMode == 1) ? g_k : g_v;
                int h = gc >> 6, d = gc & 63;
                int b0i = r0 / L, l0 = r0 % L;
                int b1i = r1 / L, l1 = r1 % L;
                float2 o0 = {v00, v01};
                float2 o1 = {v10, v11};
                *(float2*)&outHead[(((size_t)(b0i * H_ + h) * L) + l0) * DH_ + d] = o0;
                *(float2*)&outHead[(((size_t)(b1i * H_ + h) * L) + l1) * DH_ + d] = o1;
            }
        }
    }
}

// ---------------------------------------------------------------------------
// Tensor-core flash attention. Block = (64 q, h, b), 128 threads (4 warps).
// Warp w owns q rows [w*16, w*16+16). Keys tiled by 64, d = 64.
// Smem (uint32 = bf16x2):
//   Q: [64 q][32 dpairs]  stride 36     (pairs along d)
//   K: [32 dpairs][64 key] stride 72    (pairs along d)
//   V: [32 keypairs][64 d] stride 72    (pairs along key)
// P passes from S accumulators to PV A-fragments entirely in registers.
// ---------------------------------------------------------------------------
#define FS_QH 0
#define FS_QL (64 * 36)
#define FS_KH (2 * 64 * 36)
#define FS_KL (2 * 64 * 36 + 32 * 72)
#define FS_VH (2 * 64 * 36 + 2 * 32 * 72)
#define FS_VL (2 * 64 * 36 + 3 * 32 * 72)
#define FS_MSK (2 * 64 * 36 + 4 * 32 * 72)
#define FA_SMEM ((FS_MSK + 64) * 4)

__global__ __launch_bounds__(128)
void flash_attn(const int* __restrict__ mask)
{
    extern __shared__ uint32_t sm[];
    uint32_t* Qh = sm + FS_QH;
    uint32_t* Ql = sm + FS_QL;
    uint32_t* Kh = sm + FS_KH;
    uint32_t* Kl = sm + FS_KL;
    uint32_t* Vh = sm + FS_VH;
    uint32_t* Vl = sm + FS_VL;
    float*   msk = (float*)(sm + FS_MSK);

    const int q0 = blockIdx.x * 64, h = blockIdx.y, b = blockIdx.z;
    const int tid  = threadIdx.x;
    const int lane = tid & 31;
    const int w    = tid >> 5;
    const int grp  = lane >> 2;
    const int tg   = lane & 3;

    const float* qbase = g_q + ((size_t)(b * H_ + h) * LQ_ + q0) * DH_;
    const float* kbase = g_k + (size_t)(b * H_ + h) * LK_ * DH_;
    const float* vbase = g_v + (size_t)(b * H_ + h) * LK_ * DH_;

    // ---- load Q tile (once) ----
    {
        int q = tid >> 1;
        int dh = (tid & 1) * 32;
        #pragma unroll
        for (int i = 0; i < 8; i++) {
            int d = dh + i * 4;
            float4 qv = *(const float4*)&qbase[(size_t)q * DH_ + d];
            uint2 hv, lv;
            split2(qv.x, qv.y, hv.x, lv.x);
            split2(qv.z, qv.w, hv.y, lv.y);
            *(uint2*)&Qh[q * 36 + (d >> 1)] = hv;
            *(uint2*)&Ql[q * 36 + (d >> 1)] = lv;
        }
    }

    float o[8][4];
    #pragma unroll
    for (int nt = 0; nt < 8; nt++)
        #pragma unroll
        for (int j = 0; j < 4; j++) o[nt][j] = 0.f;
    float m0 = -1e30f, m1 = -1e30f, l0 = 0.f, l1 = 0.f;

    const int kq = tid & 63, kdh = (tid >> 6) * 32;     // K load mapping
    const int vkp = tid >> 2, vd0 = (tid & 3) * 16;     // V load mapping

    for (int t = 0; t < LK_ / 64; t++) {
        const int k0 = t * 64;
        __syncthreads();
        // ---- K tile: pairs along d ----
        #pragma unroll
        for (int i = 0; i < 8; i++) {
            int d = kdh + i * 4;
            float4 kv = *(const float4*)&kbase[(size_t)(k0 + kq) * DH_ + d];
            uint32_t h0, l0v, h1, l1v;
            split2(kv.x, kv.y, h0, l0v);
            split2(kv.z, kv.w, h1, l1v);
            Kh[(d >> 1) * 72 + kq] = h0;  Kh[((d >> 1) + 1) * 72 + kq] = h1;
            Kl[(d >> 1) * 72 + kq] = l0v; Kl[((d >> 1) + 1) * 72 + kq] = l1v;
        }
        // ---- V tile: pairs along key ----
        #pragma unroll
        for (int i = 0; i < 4; i++) {
            int d = vd0 + i * 4;
            const float* vr = &vbase[(size_t)(k0 + 2 * vkp) * DH_ + d];
            float4 v0 = *(const float4*)vr;
            float4 v1 = *(const float4*)(vr + DH_);
            uint4 hv, lv;
            split2(v0.x, v1.x, hv.x, lv.x);
            split2(v0.y, v1.y, hv.y, lv.y);
            split2(v0.z, v1.z, hv.z, lv.z);
            split2(v0.w, v1.w, hv.w, lv.w);
            *(uint4*)&Vh[vkp * 72 + d] = hv;
            *(uint4*)&Vl[vkp * 72 + d] = lv;
        }
        if (tid < 64) msk[tid] = (mask[b * LK_ + k0 + tid] == 0) ? -1e30f : 0.0f;
        __syncthreads();

        // ---- S = Q K^T (3-pass bf16) ----
        float s[8][4];
        #pragma unroll
        for (int nt = 0; nt < 8; nt++)
            #pragma unroll
            for (int j = 0; j < 4; j++) s[nt][j] = 0.f;

        const int r = w * 16 + grp;
        #pragma unroll
        for (int kt = 0; kt < 4; kt++) {
            const int kb = kt * 8;
            uint32_t ah0 = Qh[r * 36 + kb + tg];
            uint32_t ah1 = Qh[(r + 8) * 36 + kb + tg];
            uint32_t ah2 = Qh[r * 36 + kb + tg + 4];
            uint32_t ah3 = Qh[(r + 8) * 36 + kb + tg + 4];
            uint32_t al0 = Ql[r * 36 + kb + tg];
            uint32_t al1 = Ql[(r + 8) * 36 + kb + tg];
            uint32_t al2 = Ql[r * 36 + kb + tg + 4];
            uint32_t al3 = Ql[(r + 8) * 36 + kb + tg + 4];
            #pragma unroll
            for (int nt = 0; nt < 8; nt++) {
                int cc = nt * 8 + grp;
                uint32_t bh0 = Kh[(kb + tg) * 72 + cc];
                uint32_t bh1 = Kh[(kb + tg + 4) * 72 + cc];
                uint32_t bl0 = Kl[(kb + tg) * 72 + cc];
                uint32_t bl1 = Kl[(kb + tg + 4) * 72 + cc];
                mma_bf16(s[nt], ah0, ah1, ah2, ah3, bh0, bh1);
                mma_bf16(s[nt], ah0, ah1, ah2, ah3, bl0, bl1);
                mma_bf16(s[nt], al0, al1, al2, al3, bh0, bh1);
            }
        }

        // ---- online softmax (rows grp / grp+8; reduce over tg lanes) ----
        const float scl = 0.125f;
        float rmax0 = -1e30f, rmax1 = -1e30f;
        #pragma unroll
        for (int nt = 0; nt < 8; nt++) {
            float mk0 = msk[nt * 8 + 2 * tg];
            float mk1 = msk[nt * 8 + 2 * tg + 1];
            s[nt][0] = s[nt][0] * scl + mk0;
            s[nt][1] = s[nt][1] * scl + mk1;
            s[nt][2] = s[nt][2] * scl + mk0;
            s[nt][3] = s[nt][3] * scl + mk1;
            rmax0 = fmaxf(rmax0, fmaxf(s[nt][0], s[nt][1]));
            rmax1 = fmaxf(rmax1, fmaxf(s[nt][2], s[nt][3]));
        }
        rmax0 = fmaxf(rmax0, __shfl_xor_sync(0xffffffffu, rmax0, 1));
        rmax0 = fmaxf(rmax0, __shfl_xor_sync(0xffffffffu, rmax0, 2));
        rmax1 = fmaxf(rmax1, __shfl_xor_sync(0xffffffffu, rmax1, 1));
        rmax1 = fmaxf(rmax1, __shfl_xor_sync(0xffffffffu, rmax1, 2));

        float mn0 = fmaxf(m0, rmax0), mn1 = fmaxf(m1, rmax1);
        float c0 = __expf(m0 - mn0),  c1 = __expf(m1 - mn1);
        m0 = mn0; m1 = mn1;

        float sum0 = 0.f, sum1 = 0.f;
        #pragma unroll
        for (int nt = 0; nt < 8; nt++) {
            s[nt][0] = __expf(s[nt][0] - mn0);
            s[nt][1] = __expf(s[nt][1] - mn0);
            s[nt][2] = __expf(s[nt][2] - mn1);
            s[nt][3] = __expf(s[nt][3] - mn1);
            sum0 += s[nt][0] + s[nt][1];
            sum1 += s[nt][2] + s[nt][3];
        }
        sum0 += __shfl_xor_sync(0xffffffffu, sum0, 1);
        sum0 += __shfl_xor_sync(0xffffffffu, sum0, 2);
        sum1 += __shfl_xor_sync(0xffffffffu, sum1, 1);
        sum1 += __shfl_xor_sync(0xffffffffu, sum1, 2);
        l0 = l0 * c0 + sum0;
        l1 = l1 * c1 + sum1;

        #pragma unroll
        for (int nt = 0; nt < 8; nt++) {
            o[nt][0] *= c0; o[nt][1] *= c0;
            o[nt][2] *= c1; o[nt][3] *= c1;
        }

        // ---- O += P V (P from regs, 3-pass) ----
        #pragma unroll
        for (int kg = 0; kg < 4; kg++) {
            uint32_t ph0, ph1, ph2, ph3, pl0, pl1, pl2, pl3;
            split2(s[2 * kg][0],     s[2 * kg][1],     ph0, pl0);
            split2(s[2 * kg][2],     s[2 * kg][3],     ph1, pl1);
            split2(s[2 * kg + 1][0], s[2 * kg + 1][1], ph2, pl2);
            split2(s[2 * kg + 1][2], s[2 * kg + 1][3], ph3, pl3);
            #pragma unroll
            for (int nt = 0; nt < 8; nt++) {
                int cc = nt * 8 + grp;
                uint32_t bh0 = Vh[(kg * 8 + tg) * 72 + cc];
                uint32_t bh1 = Vh[(kg * 8 + tg + 4) * 72 + cc];
                uint32_t bl0 = Vl[(kg * 8 + tg) * 72 + cc];
                uint32_t bl1 = Vl[(kg * 8 + tg + 4) * 72 + cc];
                mma_bf16(o[nt], ph0, ph1, ph2, ph3, bh0, bh1);
                mma_bf16(o[nt], ph0, ph1, ph2, ph3, bl0, bl1);
                mma_bf16(o[nt], pl0, pl1, pl2, pl3, bh0, bh1);
            }
        }
    }

    // ---- epilogue ----
    float inv0 = 1.0f / l0, inv1 = 1.0f / l1;
    int qr0 = q0 + w * 16 + grp;
    int qr1 = qr0 + 8;
    #pragma unroll
    for (int nt = 0; nt < 8; nt++) {
        int d = nt * 8 + 2 * tg;
        float2 o0 = {o[nt][0] * inv0, o[nt][1] * inv0};
        float2 o1 = {o[nt][2] * inv1, o[nt][3] * inv1};
        *(float2*)&g_ao[((size_t)(b * LQ_ + qr0) * H_ + h) * DH_ + d] = o0;
        *(float2*)&g_ao[((size_t)(b * LQ_ + qr1) * H_ + h) * DH_ + d] = o1;
    }
}

// ---------------------------------------------------------------------------
// LayerNorm per row of g_y
// ---------------------------------------------------------------------------
__global__ void layernorm_kernel(const float* __restrict__ gamma,
                                 const float* __restrict__ beta,
                                 float* __restrict__ out)
{
    const int row = blockIdx.x;
    const int tid = threadIdx.x;
    __shared__ float red[256];

    const float* yr = g_y + (size_t)row * DM_;
    float4 xv = *(const float4*)(yr + tid * 4);

    float s = xv.x + xv.y + xv.z + xv.w;
    red[tid] = s; __syncthreads();
    #pragma unroll
    for (int st = 128; st > 0; st >>= 1) {
        if (tid < st) red[tid] += red[tid + st];
        __syncthreads();
    }
    float mean = red[0] * (1.0f / DM_);
    __syncthreads();

    float dx = xv.x - mean, dy = xv.y - mean, dz = xv.z - mean, dw = xv.w - mean;
    float sq = dx * dx + dy * dy + dz * dz + dw * dw;
    red[tid] = sq; __syncthreads();
    #pragma unroll
    for (int st = 128; st > 0; st >>= 1) {
        if (tid < st) red[tid] += red[tid + st];
        __syncthreads();
    }
    float rstd = rsqrtf(red[0] * (1.0f / DM_) + 1e-5f);

    int n = tid * 4;
    float4 ov;
    ov.x = dx * rstd * gamma[n]     + beta[n];
    ov.y = dy * rstd * gamma[n + 1] + beta[n + 1];
    ov.z = dz * rstd * gamma[n + 2] + beta[n + 2];
    ov.w = dw * rstd * gamma[n + 3] + beta[n + 3];
    *(float4*)(out + (size_t)row * DM_ + n) = ov;
}

// ---------------------------------------------------------------------------
extern "C" void kernel_launch(void* const* d_in, const int* in_sizes, int n_in,
                              void* d_out, int out_size)
{
    const float* Q    = (const float*)d_in[0];
    const float* K    = (const float*)d_in[1];
    const float* V    = (const float*)d_in[2];
    /* d_in[3] = node_num (unused) */
    const int*   mask = (const int*)  d_in[4];
    const float* Wq   = (const float*)d_in[5];
    const float* bq   = (const float*)d_in[6];
    const float* Wk   = (const float*)d_in[7];
    const float* bk   = (const float*)d_in[8];
    const float* Wv   = (const float*)d_in[9];
    const float* bv   = (const float*)d_in[10];
    const float* Wo   = (const float*)d_in[11];
    const float* bo   = (const float*)d_in[12];
    const float* gamma= (const float*)d_in[13];
    const float* beta = (const float*)d_in[14];
    float* out = (float*)d_out;

    cudaFuncSetAttribute(gemm_bf16,  cudaFuncAttributeMaxDynamicSharedMemorySize, GEMM_SMEM);
    cudaFuncSetAttribute(flash_attn, cudaFuncAttributeMaxDynamicSharedMemorySize, FA_SMEM);

    // Projections (bf16 tensor-core, 3-pass hi/lo split)
    gemm_bf16<<<dim3(DM_ / 128, (B_ * LQ_) / 128), 256, GEMM_SMEM>>>(Q, Wq, bq, nullptr, LQ_, 0);
    gemm_bf16<<<dim3(DM_ / 128, (B_ * LK_) / 128), 256, GEMM_SMEM>>>(K, Wk, bk, nullptr, LK_, 1);
    gemm_bf16<<<dim3(DM_ / 128, (B_ * LK_) / 128), 256, GEMM_SMEM>>>(V, Wv, bv, nullptr, LK_, 2);

    // Attention (tensor-core flash)
    flash_attn<<<dim3(LQ_ / 64, H_, B_), 128, FA_SMEM>>>(mask);

    // Output projection + residual
    gemm_bf16<<<dim3(DM_ / 128, (B_ * LQ_) / 128), 256, GEMM_SMEM>>>(nullptr, Wo, bo, Q, LQ_, 3);

    // LayerNorm
    layernorm_kernel<<<B_ * LQ_, 256>>>(gamma, beta, out);
}